// round 8
// baseline (speedup 1.0000x reference)
#include <cuda_runtime.h>
#include <cstdint>

// ---------------------------------------------------------------------------
// BiRNN (bidirectional masked LSTM), B=64, S=1024, D=512, U=512.
// Persistent-kernel design: 128 blocks (64 per direction), each block owns 8
// units (32 gate columns) with its [1024,32] fp32 weight slice resident in
// shared memory. One software grid barrier per direction per timestep.
// ---------------------------------------------------------------------------

namespace {
constexpr int Bk = 64;
constexpr int Sk = 1024;
constexpr int Dk = 512;
constexpr int Uk = 512;
constexpr int KT = 1024;          // D + U
constexpr int THREADS = 128;
constexpr int NBLK_DIR = 64;
constexpr int CH = 64;            // k-chunk
constexpr int NCH = KT / CH;      // 16

// shared-memory layout (in floats)
constexpr int SW_OFF  = 0;                    // [1024][32]  = 32768
constexpr int SX0_OFF = 32768;                // [64][68]    =  4352
constexpr int SX1_OFF = SX0_OFF + 64 * 68;    // 37120
constexpr int ZB_OFF  = SX1_OFF + 64 * 68;    // 41472 : [64][36] = 2304
constexpr int SC_OFF  = ZB_OFF + 64 * 36;     // 43776 : [64][8]  = 512
constexpr int SL_OFF  = SC_OFF + 512;         // 44288 : lengths (as int)
constexpr int SMEM_FLOATS = SL_OFF + 64;      // 44352
constexpr int SMEM_BYTES  = SMEM_FLOATS * 4;  // 177408 B (< 228 KB)
}

// persistent device state (re-initialized by init_kernel every launch)
__device__ __align__(16) float g_h[2][2][Bk][Uk];  // [dir][phase][b][u]
__device__ int      g_len[Bk];
__device__ unsigned g_bar[2];

// ---------------------------------------------------------------------------
// init: zero h ping-pong buffers, reset barriers, recover lengths[] from the
// mask buffer robustly across possible serializations (1-byte bool vs 4-byte
// int32/float32).
// ---------------------------------------------------------------------------
__global__ void birnn_init_kernel(const void* __restrict__ maskraw) {
    const int tid = threadIdx.x;  // 256 threads, 1 block
    float* hz = &g_h[0][0][0][0];
    for (int i = tid; i < 2 * 2 * Bk * Uk; i += 256) hz[i] = 0.0f;
    if (tid < 2) g_bar[tid] = 0u;
    if (tid < Bk) {
        const unsigned char* m8 = (const unsigned char*)maskraw;
        int cnt8 = 0;
        bool bytes_ok = true;
        for (int s = 0; s < Sk; ++s) {
            unsigned char v = m8[tid * Sk + s];
            if (v > 1) bytes_ok = false;
            cnt8 += (v != 0);
        }
        bool ok8 = bytes_ok && (cnt8 >= Sk / 2);
        if (ok8) {   // verify prefix structure
            if (m8[tid * Sk + cnt8 - 1] == 0) ok8 = false;
            else if (cnt8 < Sk && m8[tid * Sk + cnt8] != 0) ok8 = false;
        }
        int len;
        if (ok8) {
            len = cnt8;
        } else {
            // 4-byte elements: nonzero word == true (covers int32 and float32)
            const unsigned* m32 = (const unsigned*)maskraw;
            int c = 0;
            for (int s = 0; s < Sk; ++s) c += (m32[tid * Sk + s] != 0u);
            len = c;
        }
        g_len[tid] = len;
    }
}

// ---------------------------------------------------------------------------
// main persistent kernel
// ---------------------------------------------------------------------------
extern __shared__ float smem[];

__device__ __forceinline__ float sigf(float x) {
    return 1.0f / (1.0f + __expf(-x));
}

__global__ void __launch_bounds__(THREADS, 1)
birnn_kernel(const float* __restrict__ x,
             const float* __restrict__ kern_f, const float* __restrict__ rkern_f,
             const float* __restrict__ bias_f,
             const float* __restrict__ kern_b, const float* __restrict__ rkern_b,
             const float* __restrict__ bias_b,
             float* __restrict__ out) {
    const int tid  = threadIdx.x;
    const int dir  = blockIdx.x >> 6;        // 0 = fwd, 1 = bwd
    const int blk  = blockIdx.x & 63;        // block within direction
    const int ubase = blk * 8;               // 8 units per block

    const float* kern  = dir ? kern_b  : kern_f;
    const float* rkern = dir ? rkern_b : rkern_f;
    const float* bias  = dir ? bias_b  : bias_f;

    float* sW  = smem + SW_OFF;              // [k][32] (global k)
    float* sXa = smem + SX0_OFF;             // [64][68]
    float* sXb = smem + SX1_OFF;
    float* zb  = smem + ZB_OFF;              // [64][36]
    float* sC  = smem + SC_OFF;              // [64][8]
    int*   sLenI = (int*)(smem + SL_OFF);

    // ---- one-time preload: weight slice [1024][32] ----
    // col c in [0,32): gate g = c>>3, local unit ul = c&7
    for (int i = tid; i < KT * 32; i += THREADS) {
        int k = i >> 5, c = i & 31;
        int gcol = ((c >> 3) << 9) + ubase + (c & 7);     // g*512 + ubase + ul
        float v = (k < Dk) ? kern[k * 2048 + gcol]
                           : rkern[(k - Dk) * 2048 + gcol];
        sW[i] = v;
    }
    for (int i = tid; i < Bk * 8; i += THREADS) sC[i] = 0.0f;
    if (tid < Bk) sLenI[tid] = g_len[tid];

    // thread tile: 4 batches (bg + 16m) x 4 cols (4*cg .. +3)
    const int cg = tid & 7;
    const int bg = tid >> 3;
    const int c0 = 4 * cg;
    const int gcol0 = ((c0 >> 3) << 9) + ubase + (c0 & 7);
    const float4 biasv = *(const float4*)&bias[gcol0];

    __syncthreads();

    uint32_t smem_u32 = (uint32_t)__cvta_generic_to_shared(smem);
    uint32_t sx_u32[2] = { smem_u32 + (uint32_t)SX0_OFF * 4u,
                           smem_u32 + (uint32_t)SX1_OFF * 4u };

    const float* hdirbase = &g_h[dir][0][0][0];  // [phase][b][u]

    // stage one 64-k chunk of [x_t || h_t] into sX buffer (async, L2-only)
    auto issue = [&](int ci, int bufsel, int s_idx, int rp) {
        const int k0 = ci * CH;
        const float* hbase = hdirbase + (size_t)rp * Bk * Uk;
        #pragma unroll 2
        for (int i = tid; i < 1024; i += THREADS) {   // 64 b x 16 float4
            int b = i >> 4, q = i & 15;
            int k = k0 + 4 * q;
            const float* src = (k < Dk)
                ? (x + ((size_t)b * Sk + s_idx) * Dk + k)
                : (hbase + b * Uk + (k - Dk));
            uint32_t dst = sx_u32[bufsel] + (uint32_t)((b * 68 + 4 * q) * 4);
            asm volatile("cp.async.cg.shared.global [%0], [%1], 16;\n"
                         :: "r"(dst), "l"(src));
        }
        asm volatile("cp.async.commit_group;\n");
    };

    // prologue: chunk 0 of step 0 (pure x, no h dependency)
    issue(0, 0, dir ? (Sk - 1) : 0, 0);

    for (int t = 0; t < Sk; ++t) {
        const int rp = t & 1;
        const int wp = rp ^ 1;
        const int sidx = dir ? (Sk - 1 - t) : t;

        float4 acc[4];
        #pragma unroll
        for (int m = 0; m < 4; ++m) acc[m] = biasv;

        for (int ci = 0; ci < NCH; ++ci) {
            if (ci < NCH - 1) {
                issue(ci + 1, (ci + 1) & 1, sidx, rp);
                asm volatile("cp.async.wait_group 1;\n" ::: "memory");
            } else {
                asm volatile("cp.async.wait_group 0;\n" ::: "memory");
            }
            __syncthreads();   // chunk ci visible to all threads

            const float* Xc = (ci & 1) ? sXb : sXa;
            const float* Wk = sW + ci * CH * 32;

            #pragma unroll
            for (int kk = 0; kk < CH; kk += 4) {
                float4 w0 = *(const float4*)&Wk[(kk + 0) * 32 + c0];
                float4 w1 = *(const float4*)&Wk[(kk + 1) * 32 + c0];
                float4 w2 = *(const float4*)&Wk[(kk + 2) * 32 + c0];
                float4 w3 = *(const float4*)&Wk[(kk + 3) * 32 + c0];
                #pragma unroll
                for (int m = 0; m < 4; ++m) {
                    float4 xv = *(const float4*)&Xc[(bg + 16 * m) * 68 + kk];
                    float4 a = acc[m];
                    a.x = fmaf(xv.x, w0.x, a.x); a.y = fmaf(xv.x, w0.y, a.y);
                    a.z = fmaf(xv.x, w0.z, a.z); a.w = fmaf(xv.x, w0.w, a.w);
                    a.x = fmaf(xv.y, w1.x, a.x); a.y = fmaf(xv.y, w1.y, a.y);
                    a.z = fmaf(xv.y, w1.z, a.z); a.w = fmaf(xv.y, w1.w, a.w);
                    a.x = fmaf(xv.z, w2.x, a.x); a.y = fmaf(xv.z, w2.y, a.y);
                    a.z = fmaf(xv.z, w2.z, a.z); a.w = fmaf(xv.z, w2.w, a.w);
                    a.x = fmaf(xv.w, w3.x, a.x); a.y = fmaf(xv.w, w3.y, a.y);
                    a.z = fmaf(xv.w, w3.z, a.z); a.w = fmaf(xv.w, w3.w, a.w);
                    acc[m] = a;
                }
            }
            __syncthreads();   // protect buffer reuse before next issue
        }

        // prefetch chunk 0 of next step (pure x, safe before the barrier)
        if (t + 1 < Sk) issue(0, 0, dir ? (Sk - 2 - t) : (t + 1), wp);

        // ---- epilogue: gates, mask, state update ----
        #pragma unroll
        for (int m = 0; m < 4; ++m)
            *(float4*)&zb[(bg + 16 * m) * 36 + c0] = acc[m];
        __syncthreads();

        #pragma unroll
        for (int r = 0; r < 4; ++r) {
            int id = tid + r * THREADS;      // 512 tasks: (b, ul)
            int ul = id & 7, b = id >> 3;
            int ug = ubase + ul;
            float zi = zb[b * 36 + ul];
            float zf = zb[b * 36 + 8 + ul];
            float zg = zb[b * 36 + 16 + ul];
            float zo = zb[b * 36 + 24 + ul];
            float cold = sC[b * 8 + ul];
            float cn = sigf(zf) * cold + sigf(zi) * tanhf(zg);
            float hn = sigf(zo) * tanhf(cn);
            bool act = sidx < sLenI[b];
            float co = act ? cn : cold;
            float ho;
            if (act) ho = hn;
            else     ho = __ldcg(&g_h[dir][rp][b][ug]);   // carry previous h
            sC[b * 8 + ul] = co;
            __stcg(&g_h[dir][wp][b][ug], ho);
            out[((size_t)b * Sk + sidx) * (2 * Uk) + dir * Uk + ug] = ho;
        }

        __threadfence();
        __syncthreads();

        // ---- per-direction grid barrier ----
        if (tid == 0) {
            const unsigned target = (unsigned)(t + 1) * (unsigned)NBLK_DIR;
            atomicAdd(&g_bar[dir], 1u);
            volatile unsigned* p = &g_bar[dir];
            while (*p < target) { }
        }
        __syncthreads();
    }

    // ---- final states: h_f, c_f, h_b, c_b ----
    const int fin = Sk & 1;   // final write phase
    const size_t obase = (size_t)Bk * Sk * (2 * Uk);
    #pragma unroll
    for (int r = 0; r < 4; ++r) {
        int id = tid + r * THREADS;
        int ul = id & 7, b = id >> 3;
        int ug = ubase + ul;
        float hf = __ldcg(&g_h[dir][fin][b][ug]);
        float cf = sC[b * 8 + ul];
        size_t doff = obase + (size_t)dir * 2 * Bk * Uk;
        out[doff + (size_t)b * Uk + ug] = hf;                       // h
        out[doff + (size_t)Bk * Uk + (size_t)b * Uk + ug] = cf;     // c
    }
}

// ---------------------------------------------------------------------------
extern "C" void kernel_launch(void* const* d_in, const int* in_sizes, int n_in,
                              void* d_out, int out_size) {
    const float* x     = (const float*)d_in[0];
    const void*  mask  = d_in[1];
    const float* kf    = (const float*)d_in[2];
    const float* rkf   = (const float*)d_in[3];
    const float* bf    = (const float*)d_in[4];
    const float* kb    = (const float*)d_in[5];
    const float* rkb   = (const float*)d_in[6];
    const float* bb    = (const float*)d_in[7];
    float* out = (float*)d_out;

    cudaFuncSetAttribute(birnn_kernel,
                         cudaFuncAttributeMaxDynamicSharedMemorySize, SMEM_BYTES);

    birnn_init_kernel<<<1, 256>>>(mask);
    birnn_kernel<<<2 * NBLK_DIR, THREADS, SMEM_BYTES>>>(
        x, kf, rkf, bf, kb, rkb, bb, out);
}